// round 1
// baseline (speedup 1.0000x reference)
#include <cuda_runtime.h>

#define N_USERC 100000
#define N_ITEMC 50000
#define NE      1600000
#define DU      128
#define DI      64
#define HH      256

// ---------------- device scratch (no runtime allocation allowed) ----------------
__device__ int g_cnt_item[N_ITEMC];
__device__ int g_cnt_user[N_USERC];
__device__ int g_cur_item[N_ITEMC];
__device__ int g_cur_user[N_USERC];
__device__ int g_rs_item[N_ITEMC + 1];
__device__ int g_rs_user[N_USERC + 1];
__device__ int g_col_ui[NE];   // per item-dst: list of user srcs
__device__ int g_col_iu[NE];   // per user-dst: list of item srcs

__device__ float g_agg_item[(size_t)N_ITEMC * DU];   // mean of x_user per item
__device__ float g_agg_user[(size_t)N_USERC * DI];   // mean of x_item per user
__device__ float g_h_item[(size_t)N_ITEMC * HH];
__device__ float g_h_user[(size_t)N_USERC * HH];
__device__ float g_aggH_item[(size_t)N_ITEMC * HH];  // mean of h_user per item
__device__ float g_aggH_user[(size_t)N_USERC * HH];  // mean of h_item per user

// ---------------- CSR build ----------------
__global__ void count_kernel(const int* __restrict__ ui_dst, const int* __restrict__ iu_dst) {
    int i = blockIdx.x * blockDim.x + threadIdx.x;
    if (i < NE) {
        atomicAdd(&g_cnt_item[ui_dst[i]], 1);
        atomicAdd(&g_cnt_user[iu_dst[i]], 1);
    }
}

// Exclusive scan over degree arrays; block 0 -> items, block 1 -> users.
__global__ void scan_kernel() {
    const int* cnt = (blockIdx.x == 0) ? g_cnt_item : g_cnt_user;
    int*       rs  = (blockIdx.x == 0) ? g_rs_item  : g_rs_user;
    const int  n   = (blockIdx.x == 0) ? N_ITEMC    : N_USERC;

    __shared__ int sm[1024];
    __shared__ int running;
    if (threadIdx.x == 0) running = 0;
    __syncthreads();

    for (int base = 0; base < n; base += 1024) {
        int i = base + threadIdx.x;
        int v = (i < n) ? cnt[i] : 0;
        sm[threadIdx.x] = v;
        __syncthreads();
        // Hillis–Steele inclusive scan
        for (int off = 1; off < 1024; off <<= 1) {
            int t = (threadIdx.x >= (unsigned)off) ? sm[threadIdx.x - off] : 0;
            __syncthreads();
            sm[threadIdx.x] += t;
            __syncthreads();
        }
        if (i < n) rs[i] = running + sm[threadIdx.x] - v;   // exclusive
        int tot = sm[1023];
        __syncthreads();
        if (threadIdx.x == 0) running += tot;
        __syncthreads();
    }
    if (threadIdx.x == 0) rs[n] = running;
}

__global__ void fill_kernel(const int* __restrict__ ui_src, const int* __restrict__ ui_dst,
                            const int* __restrict__ iu_src, const int* __restrict__ iu_dst) {
    int i = blockIdx.x * blockDim.x + threadIdx.x;
    if (i >= NE) return;
    {
        int d = ui_dst[i];
        int p = atomicAdd(&g_cur_item[d], 1);
        g_col_ui[g_rs_item[d] + p] = ui_src[i];
    }
    {
        int d = iu_dst[i];
        int p = atomicAdd(&g_cur_user[d], 1);
        g_col_iu[g_rs_user[d] + p] = iu_src[i];
    }
}

// ---------------- gather-based segment mean ----------------
// One warp per destination row; F = NV*128 floats per row, float4 per lane per NV.
template <int NV>
__global__ __launch_bounds__(256) void agg_mean_v4(const float* __restrict__ X,
                                                   const int* __restrict__ rs,
                                                   const int* __restrict__ col,
                                                   float* __restrict__ out, int ndst) {
    int w = blockIdx.x * 8 + (threadIdx.x >> 5);
    int lane = threadIdx.x & 31;
    if (w >= ndst) return;
    int s = rs[w], e = rs[w + 1];
    constexpr int F = NV * 128;

    float4 acc0[NV], acc1[NV];
#pragma unroll
    for (int v = 0; v < NV; v++) {
        acc0[v] = make_float4(0.f, 0.f, 0.f, 0.f);
        acc1[v] = make_float4(0.f, 0.f, 0.f, 0.f);
    }
    int j = s;
    for (; j + 1 < e; j += 2) {
        const float4* r0 = (const float4*)(X + (size_t)col[j] * F);
        const float4* r1 = (const float4*)(X + (size_t)col[j + 1] * F);
#pragma unroll
        for (int v = 0; v < NV; v++) {
            float4 t0 = __ldg(&r0[lane + 32 * v]);
            float4 t1 = __ldg(&r1[lane + 32 * v]);
            acc0[v].x += t0.x; acc0[v].y += t0.y; acc0[v].z += t0.z; acc0[v].w += t0.w;
            acc1[v].x += t1.x; acc1[v].y += t1.y; acc1[v].z += t1.z; acc1[v].w += t1.w;
        }
    }
    if (j < e) {
        const float4* r0 = (const float4*)(X + (size_t)col[j] * F);
#pragma unroll
        for (int v = 0; v < NV; v++) {
            float4 t0 = __ldg(&r0[lane + 32 * v]);
            acc0[v].x += t0.x; acc0[v].y += t0.y; acc0[v].z += t0.z; acc0[v].w += t0.w;
        }
    }
    float inv = (e > s) ? 1.0f / (float)(e - s) : 0.0f;
    float4* o = (float4*)(out + (size_t)w * F);
#pragma unroll
    for (int v = 0; v < NV; v++) {
        float4 t;
        t.x = (acc0[v].x + acc1[v].x) * inv;
        t.y = (acc0[v].y + acc1[v].y) * inv;
        t.z = (acc0[v].z + acc1[v].z) * inv;
        t.w = (acc0[v].w + acc1[v].w) * inv;
        o[lane + 32 * v] = t;
    }
}

// F = 64: one float2 per lane
__global__ __launch_bounds__(256) void agg_mean_64(const float* __restrict__ X,
                                                   const int* __restrict__ rs,
                                                   const int* __restrict__ col,
                                                   float* __restrict__ out, int ndst) {
    int w = blockIdx.x * 8 + (threadIdx.x >> 5);
    int lane = threadIdx.x & 31;
    if (w >= ndst) return;
    int s = rs[w], e = rs[w + 1];
    float2 acc0 = make_float2(0.f, 0.f), acc1 = make_float2(0.f, 0.f);
    int j = s;
    for (; j + 1 < e; j += 2) {
        float2 t0 = __ldg((const float2*)(X + (size_t)col[j] * 64) + lane);
        float2 t1 = __ldg((const float2*)(X + (size_t)col[j + 1] * 64) + lane);
        acc0.x += t0.x; acc0.y += t0.y;
        acc1.x += t1.x; acc1.y += t1.y;
    }
    if (j < e) {
        float2 t0 = __ldg((const float2*)(X + (size_t)col[j] * 64) + lane);
        acc0.x += t0.x; acc0.y += t0.y;
    }
    float inv = (e > s) ? 1.0f / (float)(e - s) : 0.0f;
    float2 t = make_float2((acc0.x + acc1.x) * inv, (acc0.y + acc1.y) * inv);
    ((float2*)(out + (size_t)w * 64))[lane] = t;
}

// ---------------- fused dual-A GEMM: C = act(A1 @ W1^T + A2 @ W2^T + b) ----------------
// W stored [N, K] row-major (as given).  N = HH = 256 fixed.  BM=BN=64, BK=16,
// 256 threads, 4x4 micro-tile per thread.
template <bool RELU>
__global__ __launch_bounds__(256) void gemm_dual_kernel(
    const float* __restrict__ A1, int K1, const float* __restrict__ W1,
    const float* __restrict__ A2, int K2, const float* __restrict__ W2,
    const float* __restrict__ bias, float* __restrict__ C, int M) {
    __shared__ __align__(16) float As[16][64];
    __shared__ __align__(16) float Ws[16][64];

    const int tid = threadIdx.x;
    const int tx = tid & 15;   // n dir
    const int ty = tid >> 4;   // m dir
    const int m0 = blockIdx.x * 64;
    const int n0 = blockIdx.y * 64;
    const int lr = tid >> 2;          // load row 0..63
    const int lk = (tid & 3) * 4;     // load k offset 0,4,8,12

    float4 acc[4];
#pragma unroll
    for (int i = 0; i < 4; i++) acc[i] = make_float4(0.f, 0.f, 0.f, 0.f);

#pragma unroll 1
    for (int pass = 0; pass < 2; pass++) {
        const float* A = pass ? A2 : A1;
        const float* W = pass ? W2 : W1;
        const int K = pass ? K2 : K1;
#pragma unroll 1
        for (int k0 = 0; k0 < K; k0 += 16) {
            float4 a4 = make_float4(0.f, 0.f, 0.f, 0.f);
            if (m0 + lr < M)
                a4 = *(const float4*)(A + (size_t)(m0 + lr) * K + k0 + lk);
            float4 w4 = *(const float4*)(W + (size_t)(n0 + lr) * K + k0 + lk);
            __syncthreads();
            As[lk + 0][lr] = a4.x; As[lk + 1][lr] = a4.y;
            As[lk + 2][lr] = a4.z; As[lk + 3][lr] = a4.w;
            Ws[lk + 0][lr] = w4.x; Ws[lk + 1][lr] = w4.y;
            Ws[lk + 2][lr] = w4.z; Ws[lk + 3][lr] = w4.w;
            __syncthreads();
#pragma unroll
            for (int k = 0; k < 16; k++) {
                float4 a = *(const float4*)&As[k][ty * 4];
                float4 b = *(const float4*)&Ws[k][tx * 4];
                acc[0].x += a.x * b.x; acc[0].y += a.x * b.y; acc[0].z += a.x * b.z; acc[0].w += a.x * b.w;
                acc[1].x += a.y * b.x; acc[1].y += a.y * b.y; acc[1].z += a.y * b.z; acc[1].w += a.y * b.w;
                acc[2].x += a.z * b.x; acc[2].y += a.z * b.y; acc[2].z += a.z * b.z; acc[2].w += a.z * b.w;
                acc[3].x += a.w * b.x; acc[3].y += a.w * b.y; acc[3].z += a.w * b.z; acc[3].w += a.w * b.w;
            }
        }
    }

    float4 bv = *(const float4*)(bias + n0 + tx * 4);
#pragma unroll
    for (int i = 0; i < 4; i++) {
        int m = m0 + ty * 4 + i;
        if (m < M) {
            float4 v = acc[i];
            v.x += bv.x; v.y += bv.y; v.z += bv.z; v.w += bv.w;
            if (RELU) {
                v.x = fmaxf(v.x, 0.f); v.y = fmaxf(v.y, 0.f);
                v.z = fmaxf(v.z, 0.f); v.w = fmaxf(v.w, 0.f);
            }
            *(float4*)(C + (size_t)m * HH + n0 + tx * 4) = v;
        }
    }
}

// ---------------- host ----------------
extern "C" void kernel_launch(void* const* d_in, const int* in_sizes, int n_in,
                              void* d_out, int out_size) {
    const float* x_user = (const float*)d_in[0];
    const float* x_item = (const float*)d_in[1];
    const int* ui_src = (const int*)d_in[2];
    const int* ui_dst = (const int*)d_in[3];
    const int* iu_src = (const int*)d_in[4];
    const int* iu_dst = (const int*)d_in[5];
    const float* W1l_ui = (const float*)d_in[6];
    const float* b1_ui  = (const float*)d_in[7];
    const float* W1r_ui = (const float*)d_in[8];
    const float* W1l_iu = (const float*)d_in[9];
    const float* b1_iu  = (const float*)d_in[10];
    const float* W1r_iu = (const float*)d_in[11];
    const float* W2l_ui = (const float*)d_in[12];
    const float* b2_ui  = (const float*)d_in[13];
    const float* W2r_ui = (const float*)d_in[14];
    const float* W2l_iu = (const float*)d_in[15];
    const float* b2_iu  = (const float*)d_in[16];
    const float* W2r_iu = (const float*)d_in[17];

    int *cnt_item, *cnt_user, *cur_item, *cur_user, *rs_item, *rs_user, *col_ui, *col_iu;
    float *agg_item, *agg_user, *h_item, *h_user, *aggH_item, *aggH_user;
    cudaGetSymbolAddress((void**)&cnt_item, g_cnt_item);
    cudaGetSymbolAddress((void**)&cnt_user, g_cnt_user);
    cudaGetSymbolAddress((void**)&cur_item, g_cur_item);
    cudaGetSymbolAddress((void**)&cur_user, g_cur_user);
    cudaGetSymbolAddress((void**)&rs_item, g_rs_item);
    cudaGetSymbolAddress((void**)&rs_user, g_rs_user);
    cudaGetSymbolAddress((void**)&col_ui, g_col_ui);
    cudaGetSymbolAddress((void**)&col_iu, g_col_iu);
    cudaGetSymbolAddress((void**)&agg_item, g_agg_item);
    cudaGetSymbolAddress((void**)&agg_user, g_agg_user);
    cudaGetSymbolAddress((void**)&h_item, g_h_item);
    cudaGetSymbolAddress((void**)&h_user, g_h_user);
    cudaGetSymbolAddress((void**)&aggH_item, g_aggH_item);
    cudaGetSymbolAddress((void**)&aggH_user, g_aggH_user);

    cudaMemsetAsync(cnt_item, 0, N_ITEMC * sizeof(int), 0);
    cudaMemsetAsync(cnt_user, 0, N_USERC * sizeof(int), 0);
    cudaMemsetAsync(cur_item, 0, N_ITEMC * sizeof(int), 0);
    cudaMemsetAsync(cur_user, 0, N_USERC * sizeof(int), 0);

    // CSR build (reused by both layers)
    count_kernel<<<(NE + 255) / 256, 256>>>(ui_dst, iu_dst);
    scan_kernel<<<2, 1024>>>();
    fill_kernel<<<(NE + 255) / 256, 256>>>(ui_src, ui_dst, iu_src, iu_dst);

    // layer 1 aggregation (original feature dims)
    agg_mean_v4<1><<<(N_ITEMC + 7) / 8, 256>>>(x_user, rs_item, col_ui, agg_item, N_ITEMC);
    agg_mean_64<<<(N_USERC + 7) / 8, 256>>>(x_item, rs_user, col_iu, agg_user, N_USERC);

    // layer 1 fused GEMM + bias + relu
    gemm_dual_kernel<true><<<dim3((N_ITEMC + 63) / 64, 4), 256>>>(
        agg_item, DU, W1l_ui, x_item, DI, W1r_ui, b1_ui, h_item, N_ITEMC);
    gemm_dual_kernel<true><<<dim3((N_USERC + 63) / 64, 4), 256>>>(
        agg_user, DI, W1l_iu, x_user, DU, W1r_iu, b1_iu, h_user, N_USERC);

    // layer 2 aggregation (H = 256)
    agg_mean_v4<2><<<(N_ITEMC + 7) / 8, 256>>>(h_user, rs_item, col_ui, aggH_item, N_ITEMC);
    agg_mean_v4<2><<<(N_USERC + 7) / 8, 256>>>(h_item, rs_user, col_iu, aggH_user, N_USERC);

    // layer 2 fused GEMM + bias (output order: out_user then out_item)
    float* out_user = (float*)d_out;
    float* out_item = out_user + (size_t)N_USERC * HH;
    gemm_dual_kernel<false><<<dim3((N_ITEMC + 63) / 64, 4), 256>>>(
        aggH_item, HH, W2l_ui, h_item, HH, W2r_ui, b2_ui, out_item, N_ITEMC);
    gemm_dual_kernel<false><<<dim3((N_USERC + 63) / 64, 4), 256>>>(
        aggH_user, HH, W2l_iu, h_user, HH, W2r_iu, b2_iu, out_user, N_USERC);
}